// round 7
// baseline (speedup 1.0000x reference)
#include <cuda_runtime.h>
#include <math.h>

#define B_    64
#define T_    256
#define F_IN_ 2048
#define H_    1024
#define G3    3072
#define SPLITS 16
#define KS    (H_ / SPLITS)   // 64

// ---------------- scratch (static device allocations; no cudaMalloc) ----------
__device__ float g_emb[B_ * T_ * H_];
__device__ float g_gx [B_ * T_ * G3];
__device__ float g_cp [SPLITS * B_ * G3];      // split-K partials
__device__ float g_h  [B_ * H_];               // hidden state

// ---------------- cache-policy load/store helpers -----------------------------
// This ptxas build rejects direct .L2::evict_*.v4.f32; the createpolicy +
// .L2::cache_hint form accepts v4.f32, so use it for both policies.
__device__ __forceinline__ unsigned long long pol_evict_first() {
    unsigned long long p;
    asm("createpolicy.fractional.L2::evict_first.b64 %0, 1.0;" : "=l"(p));
    return p;
}
__device__ __forceinline__ unsigned long long pol_evict_last() {
    unsigned long long p;
    asm("createpolicy.fractional.L2::evict_last.b64 %0, 1.0;" : "=l"(p));
    return p;
}
__device__ __forceinline__ float4 ldg_pol4(const float* p, unsigned long long pol) {
    float4 v;
    asm volatile("ld.global.L2::cache_hint.v4.f32 {%0,%1,%2,%3}, [%4], %5;"
                 : "=f"(v.x), "=f"(v.y), "=f"(v.z), "=f"(v.w) : "l"(p), "l"(pol));
    return v;
}
__device__ __forceinline__ void stg_pol4(float* p, float4 v, unsigned long long pol) {
    asm volatile("st.global.L2::cache_hint.v4.f32 [%0], {%1,%2,%3,%4}, %5;"
                 :: "l"(p), "f"(v.x), "f"(v.y), "f"(v.z), "f"(v.w), "l"(pol));
}

__device__ __forceinline__ float fast_sigmoid(float x) {
    return 1.f / (1.f + __expf(-x));
}
__device__ __forceinline__ float fast_tanh(float x) {
    return 2.f / (1.f + __expf(-2.f * x)) - 1.f;
}

// ---------------- init h0 = 0 -------------------------------------------------
__global__ void zero_h_kernel() {
    int i = blockIdx.x * blockDim.x + threadIdx.x;
    if (i < B_ * H_) g_h[i] = 0.f;
}

// ---------------- big SGEMM: C[M,N] = A[M,K] @ B[N,K]^T + bias[N] -------------
__global__ __launch_bounds__(256) void sgemm_nt_bias(
    const float* __restrict__ A, const float* __restrict__ Bm,
    const float* __restrict__ bias, float* __restrict__ C,
    int M, int N, int K)
{
    __shared__ float As[16][128 + 4];
    __shared__ float Bs[16][128 + 4];
    const int tid = threadIdx.x;
    const int bm = blockIdx.y * 128;
    const int bn = blockIdx.x * 128;
    const int tx = tid & 15;
    const int ty = tid >> 4;

    float acc[8][8];
#pragma unroll
    for (int i = 0; i < 8; i++)
#pragma unroll
        for (int j = 0; j < 8; j++) acc[i][j] = 0.f;

    for (int k0 = 0; k0 < K; k0 += 16) {
#pragma unroll
        for (int l = 0; l < 2; l++) {
            int id = tid + l * 256;
            int r  = id >> 2;
            int c  = (id & 3) << 2;
            float4 va = *reinterpret_cast<const float4*>(&A[(size_t)(bm + r) * K + k0 + c]);
            As[c + 0][r] = va.x; As[c + 1][r] = va.y; As[c + 2][r] = va.z; As[c + 3][r] = va.w;
            float4 vb = *reinterpret_cast<const float4*>(&Bm[(size_t)(bn + r) * K + k0 + c]);
            Bs[c + 0][r] = vb.x; Bs[c + 1][r] = vb.y; Bs[c + 2][r] = vb.z; Bs[c + 3][r] = vb.w;
        }
        __syncthreads();
#pragma unroll
        for (int k = 0; k < 16; k++) {
            float ar[8], br[8];
            *reinterpret_cast<float4*>(ar)     = *reinterpret_cast<const float4*>(&As[k][ty * 8]);
            *reinterpret_cast<float4*>(ar + 4) = *reinterpret_cast<const float4*>(&As[k][ty * 8 + 4]);
            *reinterpret_cast<float4*>(br)     = *reinterpret_cast<const float4*>(&Bs[k][tx * 8]);
            *reinterpret_cast<float4*>(br + 4) = *reinterpret_cast<const float4*>(&Bs[k][tx * 8 + 4]);
#pragma unroll
            for (int i = 0; i < 8; i++)
#pragma unroll
                for (int j = 0; j < 8; j++)
                    acc[i][j] += ar[i] * br[j];
        }
        __syncthreads();
    }

    const int row0 = bm + ty * 8;
    const int col0 = bn + tx * 8;
    float bb[8];
#pragma unroll
    for (int j = 0; j < 8; j++) bb[j] = bias[col0 + j];
#pragma unroll
    for (int i = 0; i < 8; i++) {
        float4 v0, v1;
        v0.x = acc[i][0] + bb[0]; v0.y = acc[i][1] + bb[1];
        v0.z = acc[i][2] + bb[2]; v0.w = acc[i][3] + bb[3];
        v1.x = acc[i][4] + bb[4]; v1.y = acc[i][5] + bb[5];
        v1.z = acc[i][6] + bb[6]; v1.w = acc[i][7] + bb[7];
        *reinterpret_cast<float4*>(&C[(size_t)(row0 + i) * N + col0])     = v0;
        *reinterpret_cast<float4*>(&C[(size_t)(row0 + i) * N + col0 + 4]) = v1;
    }
}

// ---------------- per-step split-K GEMM: gh_partial = h @ w_hh^T --------------
// M=64, N=3072, K=1024 split 16 ways. BM=64, BN=128, BK=16, 8x8 micro,
// 128 threads, grid=(24,16). w_hh pinned in L2 via evict_last policy.
__global__ __launch_bounds__(128) void sgemm_step_splitk(const float* __restrict__ Whh)
{
    __shared__ float As[16][64 + 4];
    __shared__ float Bs[16][128 + 4];
    const unsigned long long pel = pol_evict_last();
    const int tid = threadIdx.x;
    const int bn = blockIdx.x * 128;
    const int s  = blockIdx.y;
    const int kbase = s * KS;
    const int tx = tid & 15;
    const int ty = tid >> 4;

    float acc[8][8];
#pragma unroll
    for (int i = 0; i < 8; i++)
#pragma unroll
        for (int j = 0; j < 8; j++) acc[i][j] = 0.f;

#pragma unroll
    for (int kk = 0; kk < KS; kk += 16) {
        const int k0 = kbase + kk;
#pragma unroll
        for (int l = 0; l < 2; l++) {        // A: 64x16 (hot, tiny)
            int id = tid + l * 128;
            int r  = id >> 2;
            int c  = (id & 3) << 2;
            float4 va = *reinterpret_cast<const float4*>(&g_h[r * H_ + k0 + c]);
            As[c + 0][r] = va.x; As[c + 1][r] = va.y; As[c + 2][r] = va.z; As[c + 3][r] = va.w;
        }
#pragma unroll
        for (int l = 0; l < 4; l++) {        // B: 128x16, pin in L2
            int id = tid + l * 128;
            int r  = id >> 2;
            int c  = (id & 3) << 2;
            float4 vb = ldg_pol4(&Whh[(size_t)(bn + r) * H_ + k0 + c], pel);
            Bs[c + 0][r] = vb.x; Bs[c + 1][r] = vb.y; Bs[c + 2][r] = vb.z; Bs[c + 3][r] = vb.w;
        }
        __syncthreads();
#pragma unroll
        for (int k = 0; k < 16; k++) {
            float ar[8], br[8];
            *reinterpret_cast<float4*>(ar)     = *reinterpret_cast<const float4*>(&As[k][ty * 8]);
            *reinterpret_cast<float4*>(ar + 4) = *reinterpret_cast<const float4*>(&As[k][ty * 8 + 4]);
            *reinterpret_cast<float4*>(br)     = *reinterpret_cast<const float4*>(&Bs[k][tx * 8]);
            *reinterpret_cast<float4*>(br + 4) = *reinterpret_cast<const float4*>(&Bs[k][tx * 8 + 4]);
#pragma unroll
            for (int i = 0; i < 8; i++)
#pragma unroll
                for (int j = 0; j < 8; j++)
                    acc[i][j] += ar[i] * br[j];
        }
        __syncthreads();
    }

    const int row0 = ty * 8;
    const int col0 = bn + tx * 8;
    float* Cp = g_cp + (size_t)s * (B_ * G3);
#pragma unroll
    for (int i = 0; i < 8; i++) {
        float4 v0, v1;
        v0.x = acc[i][0]; v0.y = acc[i][1]; v0.z = acc[i][2]; v0.w = acc[i][3];
        v1.x = acc[i][4]; v1.y = acc[i][5]; v1.z = acc[i][6]; v1.w = acc[i][7];
        *reinterpret_cast<float4*>(&Cp[(size_t)(row0 + i) * G3 + col0])     = v0;
        *reinterpret_cast<float4*>(&Cp[(size_t)(row0 + i) * G3 + col0 + 4]) = v1;
    }
}

// ---------------- gate: reduce splits, GRU nonlinearity, mask, h & y ----------
__global__ __launch_bounds__(512) void gru_gate_kernel(
    const float* __restrict__ gx, const float* __restrict__ b_hh,
    const int* __restrict__ lens, float* __restrict__ out, int t)
{
    const unsigned long long pef = pol_evict_first();
    const int v = blockIdx.x * 512 + threadIdx.x;   // 0..16383 (float4 index)
    const int b = v >> 8;
    const int j4 = (v & 255) << 2;

    float4 ghr = make_float4(0.f, 0.f, 0.f, 0.f);
    float4 ghz = ghr, ghn = ghr;
#pragma unroll
    for (int s = 0; s < SPLITS; s++) {
        const float* base = g_cp + (size_t)s * (B_ * G3) + (size_t)b * G3 + j4;
        float4 a = ldg_pol4(base, pef);
        float4 c = ldg_pol4(base + H_, pef);
        float4 d = ldg_pol4(base + 2 * H_, pef);
        ghr.x += a.x; ghr.y += a.y; ghr.z += a.z; ghr.w += a.w;
        ghz.x += c.x; ghz.y += c.y; ghz.z += c.z; ghz.w += c.w;
        ghn.x += d.x; ghn.y += d.y; ghn.z += d.z; ghn.w += d.w;
    }
    const float4 br = *reinterpret_cast<const float4*>(&b_hh[j4]);
    const float4 bz = *reinterpret_cast<const float4*>(&b_hh[H_ + j4]);
    const float4 bn = *reinterpret_cast<const float4*>(&b_hh[2 * H_ + j4]);

    const float* gxb = gx + ((size_t)b * T_ + t) * G3 + j4;
    const float4 xr = ldg_pol4(gxb, pef);
    const float4 xz = ldg_pol4(gxb + H_, pef);
    const float4 xn = ldg_pol4(gxb + 2 * H_, pef);

    const float4 hp = *reinterpret_cast<const float4*>(&g_h[b * H_ + j4]);
    const bool m = t < lens[b];

    float4 hn;
    {
        float r = fast_sigmoid(xr.x + ghr.x + br.x);
        float z = fast_sigmoid(xz.x + ghz.x + bz.x);
        float n = fast_tanh(xn.x + r * (ghn.x + bn.x));
        hn.x = (1.f - z) * n + z * hp.x;
    }
    {
        float r = fast_sigmoid(xr.y + ghr.y + br.y);
        float z = fast_sigmoid(xz.y + ghz.y + bz.y);
        float n = fast_tanh(xn.y + r * (ghn.y + bn.y));
        hn.y = (1.f - z) * n + z * hp.y;
    }
    {
        float r = fast_sigmoid(xr.z + ghr.z + br.z);
        float z = fast_sigmoid(xz.z + ghz.z + bz.z);
        float n = fast_tanh(xn.z + r * (ghn.z + bn.z));
        hn.z = (1.f - z) * n + z * hp.z;
    }
    {
        float r = fast_sigmoid(xr.w + ghr.w + br.w);
        float z = fast_sigmoid(xz.w + ghz.w + bz.w);
        float n = fast_tanh(xn.w + r * (ghn.w + bn.w));
        hn.w = (1.f - z) * n + z * hp.w;
    }

    float4 hout = m ? hn : hp;
    float4 yout = m ? hn : make_float4(0.f, 0.f, 0.f, 0.f);
    *reinterpret_cast<float4*>(&g_h[b * H_ + j4]) = hout;
    stg_pol4(&out[((size_t)b * T_ + t) * H_ + j4], yout, pef);
}

// ---------------- hidden = output[:, T-1, :] ----------------------------------
__global__ void copy_hidden_kernel(float* __restrict__ out) {
    const int idx = blockIdx.x * 1024 + threadIdx.x;
    const int b = idx >> 10;
    const int j = idx & 1023;
    out[(size_t)B_ * T_ * H_ + idx] = out[((size_t)b * T_ + (T_ - 1)) * H_ + j];
}

// ---------------- launch ------------------------------------------------------
extern "C" void kernel_launch(void* const* d_in, const int* in_sizes, int n_in,
                              void* d_out, int out_size)
{
    const float* input = (const float*)d_in[0];
    const int*   lens  = (const int*)  d_in[1];
    const float* W_p   = (const float*)d_in[2];
    const float* b_p   = (const float*)d_in[3];
    const float* w_ih  = (const float*)d_in[4];
    const float* w_hh  = (const float*)d_in[5];
    const float* b_ih  = (const float*)d_in[6];
    const float* b_hh  = (const float*)d_in[7];
    float* out = (float*)d_out;

    float *emb, *gx;
    cudaGetSymbolAddress((void**)&emb, g_emb);
    cudaGetSymbolAddress((void**)&gx,  g_gx);

    // h0 = 0
    zero_h_kernel<<<64, 1024>>>();

    // emb = input @ W_p^T + b_p          [16384 x 1024], K=2048
    dim3 g1(H_ / 128, (B_ * T_) / 128);
    sgemm_nt_bias<<<g1, 256>>>(input, W_p, b_p, emb, B_ * T_, H_, F_IN_);

    // gx = emb @ w_ih^T + b_ih           [16384 x 3072], K=1024
    dim3 g2(G3 / 128, (B_ * T_) / 128);
    sgemm_nt_bias<<<g2, 256>>>(emb, w_ih, b_ih, gx, B_ * T_, G3, H_);

    // sequential GRU scan
    dim3 gs(G3 / 128, SPLITS);
    for (int t = 0; t < T_; t++) {
        sgemm_step_splitk<<<gs, 128>>>(w_hh);
        gru_gate_kernel<<<32, 512>>>(gx, b_hh, lens, out, t);
    }

    copy_hidden_kernel<<<64, 1024>>>(out);
}

// round 9
// speedup vs baseline: 1.0872x; 1.0872x over previous
#include <cuda_runtime.h>
#include <math.h>

#define B_    64
#define T_    256
#define F_IN_ 2048
#define H_    1024
#define G3    3072
#define SPLITS 16
#define KS    (H_ / SPLITS)   // 64

// ---------------- scratch (static device allocations; no cudaMalloc) ----------
__device__ float g_emb[B_ * T_ * H_];
__device__ float g_gx [B_ * T_ * G3];
__device__ float g_cp [SPLITS * B_ * G3];      // split-K partials
__device__ float g_h  [B_ * H_];               // hidden state

__device__ __forceinline__ float fast_sigmoid(float x) {
    return 1.f / (1.f + __expf(-x));
}
__device__ __forceinline__ float fast_tanh(float x) {
    return 2.f / (1.f + __expf(-2.f * x)) - 1.f;
}

// ---------------- init h0 = 0 -------------------------------------------------
__global__ void zero_h_kernel() {
    int i = blockIdx.x * blockDim.x + threadIdx.x;
    if (i < B_ * H_) g_h[i] = 0.f;
}

// ---------------- big SGEMM (double-buffered): C = A @ B^T + bias -------------
// BM=BN=128, BK=16, 8x8 micro, 256 threads.
__global__ __launch_bounds__(256) void sgemm_nt_bias(
    const float* __restrict__ A, const float* __restrict__ Bm,
    const float* __restrict__ bias, float* __restrict__ C,
    int M, int N, int K)
{
    __shared__ float As[2][16][128 + 4];
    __shared__ float Bs[2][16][128 + 4];
    const int tid = threadIdx.x;
    const int bm = blockIdx.y * 128;
    const int bn = blockIdx.x * 128;
    const int tx = tid & 15;
    const int ty = tid >> 4;

    // loader geometry: id = tid + l*256 (l=0..1); r = id>>2 (0..127), c = (id&3)*4
    const int lr0 = tid >> 2;
    const int lc0 = (tid & 3) << 2;
    const int lr1 = (tid + 256) >> 2;
    const int lc1 = ((tid + 256) & 3) << 2;

    float acc[8][8];
#pragma unroll
    for (int i = 0; i < 8; i++)
#pragma unroll
        for (int j = 0; j < 8; j++) acc[i][j] = 0.f;

    // preload chunk 0 into buffer 0
    {
        float4 va0 = *reinterpret_cast<const float4*>(&A[(size_t)(bm + lr0) * K + lc0]);
        float4 va1 = *reinterpret_cast<const float4*>(&A[(size_t)(bm + lr1) * K + lc1]);
        float4 vb0 = *reinterpret_cast<const float4*>(&Bm[(size_t)(bn + lr0) * K + lc0]);
        float4 vb1 = *reinterpret_cast<const float4*>(&Bm[(size_t)(bn + lr1) * K + lc1]);
        As[0][lc0 + 0][lr0] = va0.x; As[0][lc0 + 1][lr0] = va0.y; As[0][lc0 + 2][lr0] = va0.z; As[0][lc0 + 3][lr0] = va0.w;
        As[0][lc1 + 0][lr1] = va1.x; As[0][lc1 + 1][lr1] = va1.y; As[0][lc1 + 2][lr1] = va1.z; As[0][lc1 + 3][lr1] = va1.w;
        Bs[0][lc0 + 0][lr0] = vb0.x; Bs[0][lc0 + 1][lr0] = vb0.y; Bs[0][lc0 + 2][lr0] = vb0.z; Bs[0][lc0 + 3][lr0] = vb0.w;
        Bs[0][lc1 + 0][lr1] = vb1.x; Bs[0][lc1 + 1][lr1] = vb1.y; Bs[0][lc1 + 2][lr1] = vb1.z; Bs[0][lc1 + 3][lr1] = vb1.w;
    }
    __syncthreads();

    const int nch = K >> 4;
    for (int ch = 0; ch < nch; ch++) {
        const int cur = ch & 1, nxt = cur ^ 1;
        float4 pa0, pa1, pb0, pb1;
        const bool more = (ch + 1 < nch);
        if (more) {
            const int k0 = (ch + 1) << 4;
            pa0 = *reinterpret_cast<const float4*>(&A[(size_t)(bm + lr0) * K + k0 + lc0]);
            pa1 = *reinterpret_cast<const float4*>(&A[(size_t)(bm + lr1) * K + k0 + lc1]);
            pb0 = *reinterpret_cast<const float4*>(&Bm[(size_t)(bn + lr0) * K + k0 + lc0]);
            pb1 = *reinterpret_cast<const float4*>(&Bm[(size_t)(bn + lr1) * K + k0 + lc1]);
        }
#pragma unroll
        for (int k = 0; k < 16; k++) {
            float ar[8], br[8];
            *reinterpret_cast<float4*>(ar)     = *reinterpret_cast<const float4*>(&As[cur][k][ty * 8]);
            *reinterpret_cast<float4*>(ar + 4) = *reinterpret_cast<const float4*>(&As[cur][k][ty * 8 + 4]);
            *reinterpret_cast<float4*>(br)     = *reinterpret_cast<const float4*>(&Bs[cur][k][tx * 8]);
            *reinterpret_cast<float4*>(br + 4) = *reinterpret_cast<const float4*>(&Bs[cur][k][tx * 8 + 4]);
#pragma unroll
            for (int i = 0; i < 8; i++)
#pragma unroll
                for (int j = 0; j < 8; j++)
                    acc[i][j] += ar[i] * br[j];
        }
        if (more) {
            As[nxt][lc0 + 0][lr0] = pa0.x; As[nxt][lc0 + 1][lr0] = pa0.y; As[nxt][lc0 + 2][lr0] = pa0.z; As[nxt][lc0 + 3][lr0] = pa0.w;
            As[nxt][lc1 + 0][lr1] = pa1.x; As[nxt][lc1 + 1][lr1] = pa1.y; As[nxt][lc1 + 2][lr1] = pa1.z; As[nxt][lc1 + 3][lr1] = pa1.w;
            Bs[nxt][lc0 + 0][lr0] = pb0.x; Bs[nxt][lc0 + 1][lr0] = pb0.y; Bs[nxt][lc0 + 2][lr0] = pb0.z; Bs[nxt][lc0 + 3][lr0] = pb0.w;
            Bs[nxt][lc1 + 0][lr1] = pb1.x; Bs[nxt][lc1 + 1][lr1] = pb1.y; Bs[nxt][lc1 + 2][lr1] = pb1.z; Bs[nxt][lc1 + 3][lr1] = pb1.w;
        }
        __syncthreads();
    }

    const int row0 = bm + ty * 8;
    const int col0 = bn + tx * 8;
    float bb[8];
#pragma unroll
    for (int j = 0; j < 8; j++) bb[j] = bias[col0 + j];
#pragma unroll
    for (int i = 0; i < 8; i++) {
        float4 v0, v1;
        v0.x = acc[i][0] + bb[0]; v0.y = acc[i][1] + bb[1];
        v0.z = acc[i][2] + bb[2]; v0.w = acc[i][3] + bb[3];
        v1.x = acc[i][4] + bb[4]; v1.y = acc[i][5] + bb[5];
        v1.z = acc[i][6] + bb[6]; v1.w = acc[i][7] + bb[7];
        *reinterpret_cast<float4*>(&C[(size_t)(row0 + i) * N + col0])     = v0;
        *reinterpret_cast<float4*>(&C[(size_t)(row0 + i) * N + col0 + 4]) = v1;
    }
}

// ---------------- per-step split-K GEMM (double-buffered) ---------------------
// gh_partial = h @ w_hh^T. M=64, N=3072, K=1024/16 splits. BM=64, BN=128,
// BK=16, 8x8 micro, 128 threads, grid=(24,16). KS=64 -> 4 chunks, unrolled.
__global__ __launch_bounds__(128) void sgemm_step_splitk(const float* __restrict__ Whh)
{
    __shared__ float As[2][16][64 + 4];
    __shared__ float Bs[2][16][128 + 4];
    const int tid = threadIdx.x;
    const int bn = blockIdx.x * 128;
    const int kbase = blockIdx.y * KS;
    const int tx = tid & 15;
    const int ty = tid >> 4;

    // A loader: ids tid, tid+128 -> 256 float4 (64x16); r=id>>2 (0..63), c=(id&3)*4
    const int ar0 = tid >> 2;
    const int ac0 = (tid & 3) << 2;
    const int ar1 = (tid + 128) >> 2;
    const int ac1 = ((tid + 128) & 3) << 2;
    // B loader: ids tid + l*128, l=0..3 -> 512 float4 (128x16)
    const int br0 = tid >> 2;          // same as ar0
    const int bc0 = (tid & 3) << 2;

    float acc[8][8];
#pragma unroll
    for (int i = 0; i < 8; i++)
#pragma unroll
        for (int j = 0; j < 8; j++) acc[i][j] = 0.f;

    // preload chunk 0
    {
        float4 va0 = *reinterpret_cast<const float4*>(&g_h[ar0 * H_ + kbase + ac0]);
        float4 va1 = *reinterpret_cast<const float4*>(&g_h[ar1 * H_ + kbase + ac1]);
        As[0][ac0 + 0][ar0] = va0.x; As[0][ac0 + 1][ar0] = va0.y; As[0][ac0 + 2][ar0] = va0.z; As[0][ac0 + 3][ar0] = va0.w;
        As[0][ac1 + 0][ar1] = va1.x; As[0][ac1 + 1][ar1] = va1.y; As[0][ac1 + 2][ar1] = va1.z; As[0][ac1 + 3][ar1] = va1.w;
#pragma unroll
        for (int l = 0; l < 4; l++) {
            int id = tid + l * 128;
            int r  = id >> 2;
            int c  = (id & 3) << 2;
            float4 vb = *reinterpret_cast<const float4*>(&Whh[(size_t)(bn + r) * H_ + kbase + c]);
            Bs[0][c + 0][r] = vb.x; Bs[0][c + 1][r] = vb.y; Bs[0][c + 2][r] = vb.z; Bs[0][c + 3][r] = vb.w;
        }
    }
    __syncthreads();

#pragma unroll
    for (int ch = 0; ch < 4; ch++) {
        const int cur = ch & 1, nxt = cur ^ 1;
        float4 pa0, pa1, pb[4];
        const bool more = (ch < 3);
        if (more) {
            const int k0 = kbase + ((ch + 1) << 4);
            pa0 = *reinterpret_cast<const float4*>(&g_h[ar0 * H_ + k0 + ac0]);
            pa1 = *reinterpret_cast<const float4*>(&g_h[ar1 * H_ + k0 + ac1]);
#pragma unroll
            for (int l = 0; l < 4; l++) {
                int id = tid + l * 128;
                int r  = id >> 2;
                int c  = (id & 3) << 2;
                pb[l] = *reinterpret_cast<const float4*>(&Whh[(size_t)(bn + r) * H_ + k0 + c]);
            }
        }
#pragma unroll
        for (int k = 0; k < 16; k++) {
            float ar[8], br[8];
            *reinterpret_cast<float4*>(ar)     = *reinterpret_cast<const float4*>(&As[cur][k][ty * 8]);
            *reinterpret_cast<float4*>(ar + 4) = *reinterpret_cast<const float4*>(&As[cur][k][ty * 8 + 4]);
            *reinterpret_cast<float4*>(br)     = *reinterpret_cast<const float4*>(&Bs[cur][k][tx * 8]);
            *reinterpret_cast<float4*>(br + 4) = *reinterpret_cast<const float4*>(&Bs[cur][k][tx * 8 + 4]);
#pragma unroll
            for (int i = 0; i < 8; i++)
#pragma unroll
                for (int j = 0; j < 8; j++)
                    acc[i][j] += ar[i] * br[j];
        }
        if (more) {
            As[nxt][ac0 + 0][ar0] = pa0.x; As[nxt][ac0 + 1][ar0] = pa0.y; As[nxt][ac0 + 2][ar0] = pa0.z; As[nxt][ac0 + 3][ar0] = pa0.w;
            As[nxt][ac1 + 0][ar1] = pa1.x; As[nxt][ac1 + 1][ar1] = pa1.y; As[nxt][ac1 + 2][ar1] = pa1.z; As[nxt][ac1 + 3][ar1] = pa1.w;
#pragma unroll
            for (int l = 0; l < 4; l++) {
                int id = tid + l * 128;
                int r  = id >> 2;
                int c  = (id & 3) << 2;
                Bs[nxt][c + 0][r] = pb[l].x; Bs[nxt][c + 1][r] = pb[l].y; Bs[nxt][c + 2][r] = pb[l].z; Bs[nxt][c + 3][r] = pb[l].w;
            }
        }
        __syncthreads();
    }

    const int row0 = ty * 8;
    const int col0 = bn + tx * 8;
    float* Cp = g_cp + (size_t)blockIdx.y * (B_ * G3);
#pragma unroll
    for (int i = 0; i < 8; i++) {
        float4 v0, v1;
        v0.x = acc[i][0]; v0.y = acc[i][1]; v0.z = acc[i][2]; v0.w = acc[i][3];
        v1.x = acc[i][4]; v1.y = acc[i][5]; v1.z = acc[i][6]; v1.w = acc[i][7];
        *reinterpret_cast<float4*>(&Cp[(size_t)(row0 + i) * G3 + col0])     = v0;
        *reinterpret_cast<float4*>(&Cp[(size_t)(row0 + i) * G3 + col0 + 4]) = v1;
    }
}

// ---------------- gate: reduce splits, GRU nonlinearity, mask, h & y ----------
__global__ __launch_bounds__(512) void gru_gate_kernel(
    const float* __restrict__ gx, const float* __restrict__ b_hh,
    const int* __restrict__ lens, float* __restrict__ out, int t)
{
    const int v = blockIdx.x * 512 + threadIdx.x;   // 0..16383 (float4 index)
    const int b = v >> 8;
    const int j4 = (v & 255) << 2;

    float4 ghr = make_float4(0.f, 0.f, 0.f, 0.f);
    float4 ghz = ghr, ghn = ghr;
#pragma unroll
    for (int s = 0; s < SPLITS; s++) {
        const float* base = g_cp + (size_t)s * (B_ * G3) + (size_t)b * G3 + j4;
        float4 a = *reinterpret_cast<const float4*>(base);
        float4 c = *reinterpret_cast<const float4*>(base + H_);
        float4 d = *reinterpret_cast<const float4*>(base + 2 * H_);
        ghr.x += a.x; ghr.y += a.y; ghr.z += a.z; ghr.w += a.w;
        ghz.x += c.x; ghz.y += c.y; ghz.z += c.z; ghz.w += c.w;
        ghn.x += d.x; ghn.y += d.y; ghn.z += d.z; ghn.w += d.w;
    }
    const float4 br = *reinterpret_cast<const float4*>(&b_hh[j4]);
    const float4 bz = *reinterpret_cast<const float4*>(&b_hh[H_ + j4]);
    const float4 bn = *reinterpret_cast<const float4*>(&b_hh[2 * H_ + j4]);

    const float* gxb = gx + ((size_t)b * T_ + t) * G3 + j4;
    const float4 xr = *reinterpret_cast<const float4*>(gxb);
    const float4 xz = *reinterpret_cast<const float4*>(gxb + H_);
    const float4 xn = *reinterpret_cast<const float4*>(gxb + 2 * H_);

    const float4 hp = *reinterpret_cast<const float4*>(&g_h[b * H_ + j4]);
    const bool m = t < lens[b];

    float4 hn;
    {
        float r = fast_sigmoid(xr.x + ghr.x + br.x);
        float z = fast_sigmoid(xz.x + ghz.x + bz.x);
        float n = fast_tanh(xn.x + r * (ghn.x + bn.x));
        hn.x = (1.f - z) * n + z * hp.x;
    }
    {
        float r = fast_sigmoid(xr.y + ghr.y + br.y);
        float z = fast_sigmoid(xz.y + ghz.y + bz.y);
        float n = fast_tanh(xn.y + r * (ghn.y + bn.y));
        hn.y = (1.f - z) * n + z * hp.y;
    }
    {
        float r = fast_sigmoid(xr.z + ghr.z + br.z);
        float z = fast_sigmoid(xz.z + ghz.z + bz.z);
        float n = fast_tanh(xn.z + r * (ghn.z + bn.z));
        hn.z = (1.f - z) * n + z * hp.z;
    }
    {
        float r = fast_sigmoid(xr.w + ghr.w + br.w);
        float z = fast_sigmoid(xz.w + ghz.w + bz.w);
        float n = fast_tanh(xn.w + r * (ghn.w + bn.w));
        hn.w = (1.f - z) * n + z * hp.w;
    }

    float4 hout = m ? hn : hp;
    float4 yout = m ? hn : make_float4(0.f, 0.f, 0.f, 0.f);
    *reinterpret_cast<float4*>(&g_h[b * H_ + j4]) = hout;
    *reinterpret_cast<float4*>(&out[((size_t)b * T_ + t) * H_ + j4]) = yout;
}

// ---------------- hidden = output[:, T-1, :] ----------------------------------
__global__ void copy_hidden_kernel(float* __restrict__ out) {
    const int idx = blockIdx.x * 1024 + threadIdx.x;
    const int b = idx >> 10;
    const int j = idx & 1023;
    out[(size_t)B_ * T_ * H_ + idx] = out[((size_t)b * T_ + (T_ - 1)) * H_ + j];
}

// ---------------- launch ------------------------------------------------------
extern "C" void kernel_launch(void* const* d_in, const int* in_sizes, int n_in,
                              void* d_out, int out_size)
{
    const float* input = (const float*)d_in[0];
    const int*   lens  = (const int*)  d_in[1];
    const float* W_p   = (const float*)d_in[2];
    const float* b_p   = (const float*)d_in[3];
    const float* w_ih  = (const float*)d_in[4];
    const float* w_hh  = (const float*)d_in[5];
    const float* b_ih  = (const float*)d_in[6];
    const float* b_hh  = (const float*)d_in[7];
    float* out = (float*)d_out;

    float *emb, *gx;
    cudaGetSymbolAddress((void**)&emb, g_emb);
    cudaGetSymbolAddress((void**)&gx,  g_gx);

    // h0 = 0
    zero_h_kernel<<<64, 1024>>>();

    // emb = input @ W_p^T + b_p          [16384 x 1024], K=2048
    dim3 g1(H_ / 128, (B_ * T_) / 128);
    sgemm_nt_bias<<<g1, 256>>>(input, W_p, b_p, emb, B_ * T_, H_, F_IN_);

    // gx = emb @ w_ih^T + b_ih           [16384 x 3072], K=1024
    dim3 g2(G3 / 128, (B_ * T_) / 128);
    sgemm_nt_bias<<<g2, 256>>>(emb, w_ih, b_ih, gx, B_ * T_, G3, H_);

    // sequential GRU scan
    dim3 gs(G3 / 128, SPLITS);
    for (int t = 0; t < T_; t++) {
        sgemm_step_splitk<<<gs, 128>>>(w_hh);
        gru_gate_kernel<<<32, 512>>>(gx, b_hh, lens, out, t);
    }

    copy_hidden_kernel<<<64, 1024>>>(out);
}

// round 10
// speedup vs baseline: 1.0943x; 1.0066x over previous
#include <cuda_runtime.h>
#include <math.h>

#define B_    64
#define T_    256
#define F_IN_ 2048
#define H_    1024
#define G3    3072
#define SPLITS 16
#define KS    (H_ / SPLITS)   // 64

#define NBLK   384            // 24 col-tiles x 16 k-splits, all co-resident
#define NTHR   128
#define SA_STRIDE 68          // 64 rows + pad, 16B-aligned rows
#define SB_STRIDE 132         // 128 cols + pad, 16B-aligned rows
#define SMEM_BYTES ((64 * SA_STRIDE + 64 * SB_STRIDE) * 4)   // 51200 B

// ---------------- scratch (static device allocations; no cudaMalloc) ----------
__device__ float g_emb[B_ * T_ * H_];
__device__ float g_gx [B_ * T_ * G3];
__device__ float g_cp [SPLITS * B_ * G3];      // split-K partials
__device__ float g_h  [B_ * H_];               // hidden state
__device__ unsigned int g_bar_count;
__device__ volatile unsigned int g_bar_gen;

__device__ __forceinline__ float fast_sigmoid(float x) {
    return 1.f / (1.f + __expf(-x));
}
__device__ __forceinline__ float fast_tanh(float x) {
    return 2.f / (1.f + __expf(-2.f * x)) - 1.f;
}

// ---------------- big SGEMM (double-buffered): C = A @ B^T + bias -------------
__global__ __launch_bounds__(256) void sgemm_nt_bias(
    const float* __restrict__ A, const float* __restrict__ Bm,
    const float* __restrict__ bias, float* __restrict__ C,
    int M, int N, int K)
{
    __shared__ float As[2][16][128 + 4];
    __shared__ float Bs[2][16][128 + 4];
    const int tid = threadIdx.x;
    const int bm = blockIdx.y * 128;
    const int bn = blockIdx.x * 128;
    const int tx = tid & 15;
    const int ty = tid >> 4;

    const int lr0 = tid >> 2;
    const int lc0 = (tid & 3) << 2;
    const int lr1 = (tid + 256) >> 2;
    const int lc1 = ((tid + 256) & 3) << 2;

    float acc[8][8];
#pragma unroll
    for (int i = 0; i < 8; i++)
#pragma unroll
        for (int j = 0; j < 8; j++) acc[i][j] = 0.f;

    {
        float4 va0 = *reinterpret_cast<const float4*>(&A[(size_t)(bm + lr0) * K + lc0]);
        float4 va1 = *reinterpret_cast<const float4*>(&A[(size_t)(bm + lr1) * K + lc1]);
        float4 vb0 = *reinterpret_cast<const float4*>(&Bm[(size_t)(bn + lr0) * K + lc0]);
        float4 vb1 = *reinterpret_cast<const float4*>(&Bm[(size_t)(bn + lr1) * K + lc1]);
        As[0][lc0 + 0][lr0] = va0.x; As[0][lc0 + 1][lr0] = va0.y; As[0][lc0 + 2][lr0] = va0.z; As[0][lc0 + 3][lr0] = va0.w;
        As[0][lc1 + 0][lr1] = va1.x; As[0][lc1 + 1][lr1] = va1.y; As[0][lc1 + 2][lr1] = va1.z; As[0][lc1 + 3][lr1] = va1.w;
        Bs[0][lc0 + 0][lr0] = vb0.x; Bs[0][lc0 + 1][lr0] = vb0.y; Bs[0][lc0 + 2][lr0] = vb0.z; Bs[0][lc0 + 3][lr0] = vb0.w;
        Bs[0][lc1 + 0][lr1] = vb1.x; Bs[0][lc1 + 1][lr1] = vb1.y; Bs[0][lc1 + 2][lr1] = vb1.z; Bs[0][lc1 + 3][lr1] = vb1.w;
    }
    __syncthreads();

    const int nch = K >> 4;
    for (int ch = 0; ch < nch; ch++) {
        const int cur = ch & 1, nxt = cur ^ 1;
        float4 pa0, pa1, pb0, pb1;
        const bool more = (ch + 1 < nch);
        if (more) {
            const int k0 = (ch + 1) << 4;
            pa0 = *reinterpret_cast<const float4*>(&A[(size_t)(bm + lr0) * K + k0 + lc0]);
            pa1 = *reinterpret_cast<const float4*>(&A[(size_t)(bm + lr1) * K + k0 + lc1]);
            pb0 = *reinterpret_cast<const float4*>(&Bm[(size_t)(bn + lr0) * K + k0 + lc0]);
            pb1 = *reinterpret_cast<const float4*>(&Bm[(size_t)(bn + lr1) * K + k0 + lc1]);
        }
#pragma unroll
        for (int k = 0; k < 16; k++) {
            float ar[8], br[8];
            *reinterpret_cast<float4*>(ar)     = *reinterpret_cast<const float4*>(&As[cur][k][ty * 8]);
            *reinterpret_cast<float4*>(ar + 4) = *reinterpret_cast<const float4*>(&As[cur][k][ty * 8 + 4]);
            *reinterpret_cast<float4*>(br)     = *reinterpret_cast<const float4*>(&Bs[cur][k][tx * 8]);
            *reinterpret_cast<float4*>(br + 4) = *reinterpret_cast<const float4*>(&Bs[cur][k][tx * 8 + 4]);
#pragma unroll
            for (int i = 0; i < 8; i++)
#pragma unroll
                for (int j = 0; j < 8; j++)
                    acc[i][j] += ar[i] * br[j];
        }
        if (more) {
            As[nxt][lc0 + 0][lr0] = pa0.x; As[nxt][lc0 + 1][lr0] = pa0.y; As[nxt][lc0 + 2][lr0] = pa0.z; As[nxt][lc0 + 3][lr0] = pa0.w;
            As[nxt][lc1 + 0][lr1] = pa1.x; As[nxt][lc1 + 1][lr1] = pa1.y; As[nxt][lc1 + 2][lr1] = pa1.z; As[nxt][lc1 + 3][lr1] = pa1.w;
            Bs[nxt][lc0 + 0][lr0] = pb0.x; Bs[nxt][lc0 + 1][lr0] = pb0.y; Bs[nxt][lc0 + 2][lr0] = pb0.z; Bs[nxt][lc0 + 3][lr0] = pb0.w;
            Bs[nxt][lc1 + 0][lr1] = pb1.x; Bs[nxt][lc1 + 1][lr1] = pb1.y; Bs[nxt][lc1 + 2][lr1] = pb1.z; Bs[nxt][lc1 + 3][lr1] = pb1.w;
        }
        __syncthreads();
    }

    const int row0 = bm + ty * 8;
    const int col0 = bn + tx * 8;
    float bb[8];
#pragma unroll
    for (int j = 0; j < 8; j++) bb[j] = bias[col0 + j];
#pragma unroll
    for (int i = 0; i < 8; i++) {
        float4 v0, v1;
        v0.x = acc[i][0] + bb[0]; v0.y = acc[i][1] + bb[1];
        v0.z = acc[i][2] + bb[2]; v0.w = acc[i][3] + bb[3];
        v1.x = acc[i][4] + bb[4]; v1.y = acc[i][5] + bb[5];
        v1.z = acc[i][6] + bb[6]; v1.w = acc[i][7] + bb[7];
        *reinterpret_cast<float4*>(&C[(size_t)(row0 + i) * N + col0])     = v0;
        *reinterpret_cast<float4*>(&C[(size_t)(row0 + i) * N + col0 + 4]) = v1;
    }
}

// ---------------- grid-wide barrier ------------------------------------------
__device__ __forceinline__ void grid_barrier()
{
    __syncthreads();
    if (threadIdx.x == 0) {
        __threadfence();
        unsigned int gen = g_bar_gen;
        unsigned int t = atomicAdd(&g_bar_count, 1u);
        if (t == NBLK - 1) {
            g_bar_count = 0;
            __threadfence();
            g_bar_gen = gen + 1;
        } else {
            while (g_bar_gen == gen) { }
        }
        __threadfence();
    }
    __syncthreads();
}

// ---------------- persistent GRU scan with SMEM-resident w_hh -----------------
// Block bid owns w_hh cols [bn, bn+128) x k [kbase, kbase+64) in smem forever.
// Per step: stage h slice -> GEMM tile -> partials; barrier; gate; barrier.
__global__ void __launch_bounds__(NTHR, 3) gru_scan_persistent(
    const float* __restrict__ gx, const float* __restrict__ Whh,
    const float* __restrict__ b_hh, const int* __restrict__ lens,
    float* __restrict__ out)
{
    extern __shared__ float smem[];
    float* sA = smem;                    // [64][SA_STRIDE]  h slice (k-major)
    float* sB = smem + 64 * SA_STRIDE;   // [64][SB_STRIDE]  w_hh slab (k-major)

    const int bid = blockIdx.x;
    const int tid = threadIdx.x;
    const int gtid = bid * NTHR + tid;
    const int tx = tid & 15;             // col micro
    const int ty = tid >> 4;             // row micro
    const int bn = (bid % 24) * 128;
    const int kbase = (bid / 24) * KS;
    const int sp = bid / 24;

    // ---- load w_hh slab into smem ONCE: sB[k][col] = Whh[bn+col][kbase+k] ----
    for (int i = tid; i < 128 * 16; i += NTHR) {
        const int col = i >> 4;
        const int k4  = (i & 15) << 2;
        const float4 w = __ldcg(reinterpret_cast<const float4*>(
            &Whh[(size_t)(bn + col) * H_ + kbase + k4]));
        sB[(k4 + 0) * SB_STRIDE + col] = w.x;
        sB[(k4 + 1) * SB_STRIDE + col] = w.y;
        sB[(k4 + 2) * SB_STRIDE + col] = w.z;
        sB[(k4 + 3) * SB_STRIDE + col] = w.w;
    }

    // ---- h0 = 0 ----
    for (int i = gtid; i < B_ * H_; i += NBLK * NTHR) g_h[i] = 0.f;
    grid_barrier();

    float* Cp = g_cp + (size_t)sp * (B_ * G3);

    for (int t = 0; t < T_; t++) {
        // ======== phase A: stage h slice, GEMM tile ========
        for (int i = tid; i < 64 * 16; i += NTHR) {
            const int r  = i >> 4;
            const int k4 = (i & 15) << 2;
            const float4 a = __ldcg(reinterpret_cast<const float4*>(
                &g_h[r * H_ + kbase + k4]));
            sA[(k4 + 0) * SA_STRIDE + r] = a.x;
            sA[(k4 + 1) * SA_STRIDE + r] = a.y;
            sA[(k4 + 2) * SA_STRIDE + r] = a.z;
            sA[(k4 + 3) * SA_STRIDE + r] = a.w;
        }
        __syncthreads();

        float acc[8][8];
#pragma unroll
        for (int i = 0; i < 8; i++)
#pragma unroll
            for (int j = 0; j < 8; j++) acc[i][j] = 0.f;

#pragma unroll 4
        for (int k = 0; k < KS; k++) {
            float ar[8], br[8];
            *reinterpret_cast<float4*>(ar)     = *reinterpret_cast<const float4*>(&sA[k * SA_STRIDE + ty * 8]);
            *reinterpret_cast<float4*>(ar + 4) = *reinterpret_cast<const float4*>(&sA[k * SA_STRIDE + ty * 8 + 4]);
            *reinterpret_cast<float4*>(br)     = *reinterpret_cast<const float4*>(&sB[k * SB_STRIDE + tx * 8]);
            *reinterpret_cast<float4*>(br + 4) = *reinterpret_cast<const float4*>(&sB[k * SB_STRIDE + tx * 8 + 4]);
#pragma unroll
            for (int i = 0; i < 8; i++)
#pragma unroll
                for (int j = 0; j < 8; j++)
                    acc[i][j] += ar[i] * br[j];
        }

        const int row0 = ty * 8;
        const int col0 = bn + tx * 8;
#pragma unroll
        for (int i = 0; i < 8; i++) {
            float4 v0, v1;
            v0.x = acc[i][0]; v0.y = acc[i][1]; v0.z = acc[i][2]; v0.w = acc[i][3];
            v1.x = acc[i][4]; v1.y = acc[i][5]; v1.z = acc[i][6]; v1.w = acc[i][7];
            __stcg(reinterpret_cast<float4*>(&Cp[(size_t)(row0 + i) * G3 + col0]), v0);
            __stcg(reinterpret_cast<float4*>(&Cp[(size_t)(row0 + i) * G3 + col0 + 4]), v1);
        }
        __syncthreads();   // sA reuse safety before next stage (after barrier anyway)
        grid_barrier();

        // ======== phase B: reduce + gates + update (first 16384 threads) ======
        if (gtid < 16384) {
            const int v = gtid;
            const int b = v >> 8;
            const int j4 = (v & 255) << 2;

            float4 ghr = make_float4(0.f, 0.f, 0.f, 0.f);
            float4 ghz = ghr, ghn = ghr;
#pragma unroll
            for (int s = 0; s < SPLITS; s++) {
                const float* base = g_cp + (size_t)s * (B_ * G3) + (size_t)b * G3 + j4;
                const float4 a = __ldcg(reinterpret_cast<const float4*>(base));
                const float4 c = __ldcg(reinterpret_cast<const float4*>(base + H_));
                const float4 d = __ldcg(reinterpret_cast<const float4*>(base + 2 * H_));
                ghr.x += a.x; ghr.y += a.y; ghr.z += a.z; ghr.w += a.w;
                ghz.x += c.x; ghz.y += c.y; ghz.z += c.z; ghz.w += c.w;
                ghn.x += d.x; ghn.y += d.y; ghn.z += d.z; ghn.w += d.w;
            }
            const float4 br = *reinterpret_cast<const float4*>(&b_hh[j4]);
            const float4 bz = *reinterpret_cast<const float4*>(&b_hh[H_ + j4]);
            const float4 bn2 = *reinterpret_cast<const float4*>(&b_hh[2 * H_ + j4]);

            const float* gxb = gx + ((size_t)b * T_ + t) * G3 + j4;
            const float4 xr = __ldcg(reinterpret_cast<const float4*>(gxb));
            const float4 xz = __ldcg(reinterpret_cast<const float4*>(gxb + H_));
            const float4 xn = __ldcg(reinterpret_cast<const float4*>(gxb + 2 * H_));

            const float4 hp = __ldcg(reinterpret_cast<const float4*>(&g_h[b * H_ + j4]));
            const bool m = t < lens[b];

            float4 hn;
            {
                float r = fast_sigmoid(xr.x + ghr.x + br.x);
                float z = fast_sigmoid(xz.x + ghz.x + bz.x);
                float n = fast_tanh(xn.x + r * (ghn.x + bn2.x));
                hn.x = (1.f - z) * n + z * hp.x;
            }
            {
                float r = fast_sigmoid(xr.y + ghr.y + br.y);
                float z = fast_sigmoid(xz.y + ghz.y + bz.y);
                float n = fast_tanh(xn.y + r * (ghn.y + bn2.y));
                hn.y = (1.f - z) * n + z * hp.y;
            }
            {
                float r = fast_sigmoid(xr.z + ghr.z + br.z);
                float z = fast_sigmoid(xz.z + ghz.z + bz.z);
                float n = fast_tanh(xn.z + r * (ghn.z + bn2.z));
                hn.z = (1.f - z) * n + z * hp.z;
            }
            {
                float r = fast_sigmoid(xr.w + ghr.w + br.w);
                float z = fast_sigmoid(xz.w + ghz.w + bz.w);
                float n = fast_tanh(xn.w + r * (ghn.w + bn2.w));
                hn.w = (1.f - z) * n + z * hp.w;
            }

            const float4 hout = m ? hn : hp;
            const float4 yout = m ? hn : make_float4(0.f, 0.f, 0.f, 0.f);
            __stcg(reinterpret_cast<float4*>(&g_h[b * H_ + j4]), hout);
            __stcg(reinterpret_cast<float4*>(&out[((size_t)b * T_ + t) * H_ + j4]), yout);
        }
        grid_barrier();
    }

    // hidden = output[:, T-1, :]
    for (int idx = gtid; idx < B_ * H_; idx += NBLK * NTHR) {
        const int b = idx >> 10;
        const int j = idx & 1023;
        out[(size_t)B_ * T_ * H_ + idx] =
            __ldcg(&out[((size_t)b * T_ + (T_ - 1)) * H_ + j]);
    }
}

// ---------------- launch ------------------------------------------------------
extern "C" void kernel_launch(void* const* d_in, const int* in_sizes, int n_in,
                              void* d_out, int out_size)
{
    const float* input = (const float*)d_in[0];
    const int*   lens  = (const int*)  d_in[1];
    const float* W_p   = (const float*)d_in[2];
    const float* b_p   = (const float*)d_in[3];
    const float* w_ih  = (const float*)d_in[4];
    const float* w_hh  = (const float*)d_in[5];
    const float* b_ih  = (const float*)d_in[6];
    const float* b_hh  = (const float*)d_in[7];
    float* out = (float*)d_out;

    float *emb, *gx;
    cudaGetSymbolAddress((void**)&emb, g_emb);
    cudaGetSymbolAddress((void**)&gx,  g_gx);

    // emb = input @ W_p^T + b_p          [16384 x 1024], K=2048
    dim3 g1(H_ / 128, (B_ * T_) / 128);
    sgemm_nt_bias<<<g1, 256>>>(input, W_p, b_p, emb, B_ * T_, H_, F_IN_);

    // gx = emb @ w_ih^T + b_ih           [16384 x 3072], K=1024
    dim3 g2(G3 / 128, (B_ * T_) / 128);
    sgemm_nt_bias<<<g2, 256>>>(emb, w_ih, b_ih, gx, B_ * T_, G3, H_);

    // persistent fused scan (h0 init + 256 steps + hidden copy)
    static int smem_set = 0;
    if (!smem_set) {
        cudaFuncSetAttribute(gru_scan_persistent,
                             cudaFuncAttributeMaxDynamicSharedMemorySize, SMEM_BYTES);
        smem_set = 1;
    }
    gru_scan_persistent<<<NBLK, NTHR, SMEM_BYTES>>>(gx, w_hh, b_hh, lens, out);
}